// round 1
// baseline (speedup 1.0000x reference)
#include <cuda_runtime.h>
#include <math.h>

// Problem constants: B=32, SD=SE=512, D=512
#define BATCH 32
#define SEQ   512
#define DIM   512

#define BM 128
#define BN 128
#define BK 8
#define TM 8
#define TN 8
// 256 threads = 16x16 thread tile, each thread computes 8x8

// scratch for attention context (32*512*512 floats = 32 MiB, static device mem)
__device__ float g_ctx[(size_t)BATCH * SEQ * DIM];

// ---------------------------------------------------------------------------
// K1: scores[b,q,k] = alpha * sum_d Q[b,q,d] * K[b,k,d]   (batched NT GEMM)
// M=N=Kdim=512 per batch.
// ---------------------------------------------------------------------------
__global__ __launch_bounds__(256) void k_scores_nt(
    const float* __restrict__ Q, const float* __restrict__ Kenc,
    float* __restrict__ C, float alpha)
{
    const int b = blockIdx.z;
    const float* A = Q    + (size_t)b * SEQ * DIM;
    const float* B = Kenc + (size_t)b * SEQ * DIM;
    float*       Cb = C   + (size_t)b * SEQ * SEQ;

    __shared__ float As[BK][BM];
    __shared__ float Bs[BK][BN];

    const int tid = threadIdx.x;
    const int tx = tid & 15;
    const int ty = tid >> 4;
    const int rowA = blockIdx.y * BM;
    const int rowB = blockIdx.x * BN;

    const int lr = tid >> 1;         // 0..127 : row within tile
    const int lc = (tid & 1) * 4;    // 0 or 4 : col group (float4)

    float acc[TM][TN];
#pragma unroll
    for (int i = 0; i < TM; i++)
#pragma unroll
        for (int j = 0; j < TN; j++) acc[i][j] = 0.f;

    for (int k0 = 0; k0 < DIM; k0 += BK) {
        float4 av = *(const float4*)&A[(size_t)(rowA + lr) * DIM + k0 + lc];
        As[lc + 0][lr] = av.x; As[lc + 1][lr] = av.y;
        As[lc + 2][lr] = av.z; As[lc + 3][lr] = av.w;
        float4 bv = *(const float4*)&B[(size_t)(rowB + lr) * DIM + k0 + lc];
        Bs[lc + 0][lr] = bv.x; Bs[lc + 1][lr] = bv.y;
        Bs[lc + 2][lr] = bv.z; Bs[lc + 3][lr] = bv.w;
        __syncthreads();
#pragma unroll
        for (int k = 0; k < BK; k++) {
            float ar[TM], br[TN];
#pragma unroll
            for (int i = 0; i < TM; i++) ar[i] = As[k][ty * TM + i];
#pragma unroll
            for (int j = 0; j < TN; j++) br[j] = Bs[k][tx * TN + j];
#pragma unroll
            for (int i = 0; i < TM; i++)
#pragma unroll
                for (int j = 0; j < TN; j++) acc[i][j] += ar[i] * br[j];
        }
        __syncthreads();
    }

#pragma unroll
    for (int i = 0; i < TM; i++) {
        int m = rowA + ty * TM + i;
#pragma unroll
        for (int j = 0; j < TN; j += 4) {
            float4 v;
            v.x = acc[i][j + 0] * alpha;
            v.y = acc[i][j + 1] * alpha;
            v.z = acc[i][j + 2] * alpha;
            v.w = acc[i][j + 3] * alpha;
            *(float4*)&Cb[(size_t)m * SEQ + rowB + tx * TN + j] = v;
        }
    }
}

// ---------------------------------------------------------------------------
// K2: row softmax in place. One block per row (B*SD = 16384 rows), 256 thr.
// ---------------------------------------------------------------------------
__global__ __launch_bounds__(256) void k_softmax(float* __restrict__ w)
{
    float* row = w + (size_t)blockIdx.x * SEQ;
    const int t = threadIdx.x;

    float a = row[t];
    float b = row[t + 256];

    __shared__ float red[8];

    // max
    float m = fmaxf(a, b);
#pragma unroll
    for (int o = 16; o > 0; o >>= 1)
        m = fmaxf(m, __shfl_xor_sync(0xffffffffu, m, o));
    if ((t & 31) == 0) red[t >> 5] = m;
    __syncthreads();
    float M = fmaxf(fmaxf(fmaxf(red[0], red[1]), fmaxf(red[2], red[3])),
                    fmaxf(fmaxf(red[4], red[5]), fmaxf(red[6], red[7])));
    __syncthreads();

    float e0 = __expf(a - M);
    float e1 = __expf(b - M);

    // sum
    float s = e0 + e1;
#pragma unroll
    for (int o = 16; o > 0; o >>= 1)
        s += __shfl_xor_sync(0xffffffffu, s, o);
    if ((t & 31) == 0) red[t >> 5] = s;
    __syncthreads();
    float S = red[0] + red[1] + red[2] + red[3] +
              red[4] + red[5] + red[6] + red[7];

    float inv = 1.0f / S;
    row[t]       = e0 * inv;
    row[t + 256] = e1 * inv;
}

// ---------------------------------------------------------------------------
// K3: ctx[b,q,d] = sum_k Wgt[b,q,k] * Enc[b,k,d]   (batched NN GEMM)
// ---------------------------------------------------------------------------
__global__ __launch_bounds__(256) void k_ctx_nn(
    const float* __restrict__ Wgt, const float* __restrict__ Enc)
{
    const int b = blockIdx.z;
    const float* A = Wgt + (size_t)b * SEQ * SEQ;
    const float* B = Enc + (size_t)b * SEQ * DIM;
    float*       Cb = g_ctx + (size_t)b * SEQ * DIM;

    __shared__ float As[BK][BM];
    __shared__ float Bs[BK][BN];

    const int tid = threadIdx.x;
    const int tx = tid & 15;
    const int ty = tid >> 4;
    const int rowA = blockIdx.y * BM;
    const int colB = blockIdx.x * BN;

    const int lar = tid >> 1;        // 0..127
    const int lac = (tid & 1) * 4;   // 0 or 4
    const int lbr = tid >> 5;        // 0..7  (k within tile)
    const int lbc = (tid & 31) * 4;  // 0..124

    float acc[TM][TN];
#pragma unroll
    for (int i = 0; i < TM; i++)
#pragma unroll
        for (int j = 0; j < TN; j++) acc[i][j] = 0.f;

    for (int k0 = 0; k0 < SEQ; k0 += BK) {
        float4 av = *(const float4*)&A[(size_t)(rowA + lar) * SEQ + k0 + lac];
        As[lac + 0][lar] = av.x; As[lac + 1][lar] = av.y;
        As[lac + 2][lar] = av.z; As[lac + 3][lar] = av.w;
        float4 bv = *(const float4*)&B[(size_t)(k0 + lbr) * DIM + colB + lbc];
        *(float4*)&Bs[lbr][lbc] = bv;
        __syncthreads();
#pragma unroll
        for (int k = 0; k < BK; k++) {
            float ar[TM], br[TN];
#pragma unroll
            for (int i = 0; i < TM; i++) ar[i] = As[k][ty * TM + i];
#pragma unroll
            for (int j = 0; j < TN; j++) br[j] = Bs[k][tx * TN + j];
#pragma unroll
            for (int i = 0; i < TM; i++)
#pragma unroll
                for (int j = 0; j < TN; j++) acc[i][j] += ar[i] * br[j];
        }
        __syncthreads();
    }

#pragma unroll
    for (int i = 0; i < TM; i++) {
        int m = rowA + ty * TM + i;
#pragma unroll
        for (int j = 0; j < TN; j += 4) {
            float4 v;
            v.x = acc[i][j + 0]; v.y = acc[i][j + 1];
            v.z = acc[i][j + 2]; v.w = acc[i][j + 3];
            *(float4*)&Cb[(size_t)m * DIM + colB + tx * TN + j] = v;
        }
    }
}

// ---------------------------------------------------------------------------
// K4: out[m,n] = tanh( sum_{k<512} Q[m,k]W[n,k] + sum_{k<512} ctx[m,k]W[n,512+k]
//                      + bias[n] ) * mask[m]
// M = B*SD = 16384, N = 512, Kdim = 1024 (virtual concat; never materialized)
// W is (512, 1024) row-major -> NT GEMM against W rows.
// ---------------------------------------------------------------------------
__global__ __launch_bounds__(256) void k_final_nt(
    const float* __restrict__ Q, const float* __restrict__ W,
    const float* __restrict__ bias, const float* __restrict__ dmask,
    float* __restrict__ out)
{
    __shared__ float As[BK][BM];
    __shared__ float Bs[BK][BN];

    const int tid = threadIdx.x;
    const int tx = tid & 15;
    const int ty = tid >> 4;
    const int rowA = blockIdx.y * BM;   // m tile (0..16383)
    const int rowB = blockIdx.x * BN;   // n tile (0..511)

    const int lr = tid >> 1;
    const int lc = (tid & 1) * 4;

    float acc[TM][TN];
#pragma unroll
    for (int i = 0; i < TM; i++)
#pragma unroll
        for (int j = 0; j < TN; j++) acc[i][j] = 0.f;

    for (int k0 = 0; k0 < 2 * DIM; k0 += BK) {
        // virtual concat: first 512 cols from Q, next 512 from g_ctx
        const float* Asrc = (k0 < DIM) ? Q : g_ctx;
        const int kc = (k0 < DIM) ? k0 : (k0 - DIM);
        float4 av = *(const float4*)&Asrc[(size_t)(rowA + lr) * DIM + kc + lc];
        As[lc + 0][lr] = av.x; As[lc + 1][lr] = av.y;
        As[lc + 2][lr] = av.z; As[lc + 3][lr] = av.w;
        float4 bv = *(const float4*)&W[(size_t)(rowB + lr) * (2 * DIM) + k0 + lc];
        Bs[lc + 0][lr] = bv.x; Bs[lc + 1][lr] = bv.y;
        Bs[lc + 2][lr] = bv.z; Bs[lc + 3][lr] = bv.w;
        __syncthreads();
#pragma unroll
        for (int k = 0; k < BK; k++) {
            float ar[TM], br[TN];
#pragma unroll
            for (int i = 0; i < TM; i++) ar[i] = As[k][ty * TM + i];
#pragma unroll
            for (int j = 0; j < TN; j++) br[j] = Bs[k][tx * TN + j];
#pragma unroll
            for (int i = 0; i < TM; i++)
#pragma unroll
                for (int j = 0; j < TN; j++) acc[i][j] += ar[i] * br[j];
        }
        __syncthreads();
    }

    float bj[TN];
#pragma unroll
    for (int j = 0; j < TN; j++) bj[j] = bias[rowB + tx * TN + j];

#pragma unroll
    for (int i = 0; i < TM; i++) {
        int m = rowA + ty * TM + i;
        float msk = dmask[m];
#pragma unroll
        for (int j = 0; j < TN; j += 4) {
            float4 v;
            v.x = tanhf(acc[i][j + 0] + bj[j + 0]) * msk;
            v.y = tanhf(acc[i][j + 1] + bj[j + 1]) * msk;
            v.z = tanhf(acc[i][j + 2] + bj[j + 2]) * msk;
            v.w = tanhf(acc[i][j + 3] + bj[j + 3]) * msk;
            *(float4*)&out[(size_t)m * DIM + rowB + tx * TN + j] = v;
        }
    }
}

// ---------------------------------------------------------------------------
extern "C" void kernel_launch(void* const* d_in, const int* in_sizes, int n_in,
                              void* d_out, int out_size)
{
    const float* Q    = (const float*)d_in[0];  // (32,512,512)
    const float* Enc  = (const float*)d_in[1];  // (32,512,512)
    const float* mask = (const float*)d_in[2];  // (32,512,1)
    const float* W    = (const float*)d_in[3];  // (512,1024)
    const float* bias = (const float*)d_in[4];  // (512,)

    float* out_masked  = (float*)d_out;                                   // (32,512,512)
    float* out_weights = (float*)d_out + (size_t)BATCH * SEQ * SEQ;       // (32,512,512)

    const float alpha = 1.0f / sqrtf((float)DIM);

    // K1: scores -> out_weights
    {
        dim3 grid(SEQ / BN, SEQ / BM, BATCH);
        k_scores_nt<<<grid, 256>>>(Q, Enc, out_weights, alpha);
    }
    // K2: softmax in place
    {
        k_softmax<<<BATCH * SEQ, 256>>>(out_weights);
    }
    // K3: ctx = weights @ Enc  -> g_ctx
    {
        dim3 grid(DIM / BN, SEQ / BM, BATCH);
        k_ctx_nn<<<grid, 256>>>(out_weights, Enc);
    }
    // K4: out = tanh([Q,ctx] @ W^T + b) * mask
    {
        dim3 grid(DIM / BN, (BATCH * SEQ) / BM, 1);
        k_final_nt<<<grid, 256>>>(Q, W, bias, mask, out_masked);
    }
}

// round 3
// speedup vs baseline: 2.5852x; 2.5852x over previous
#include <cuda_runtime.h>
#include <cuda_bf16.h>
#include <cstdint>
#include <math.h>

#define BATCH 32
#define SEQ   512
#define DIM   512

using bf16 = __nv_bfloat16;

// ---------------- scratch (static device memory; no allocations) ------------
#define NELEM ((size_t)BATCH * SEQ * DIM)          // 8,388,608
__device__ __align__(16) bf16 g_qh[NELEM], g_ql[NELEM];     // Q hi/lo      [b,q,d]
__device__ __align__(16) bf16 g_eh[NELEM], g_el[NELEM];     // Enc hi/lo    [b,e,d]
__device__ __align__(16) bf16 g_eth[NELEM], g_etl[NELEM];   // EncT hi/lo   [b,d,e]
__device__ __align__(16) bf16 g_awh[NELEM], g_awl[NELEM];   // attn weights [b,q,e]
__device__ __align__(16) bf16 g_ch[NELEM], g_cl[NELEM];     // ctx hi/lo    [b,q,d]
__device__ __align__(16) bf16 g_wh[(size_t)DIM * 2 * DIM], g_wl[(size_t)DIM * 2 * DIM];

// ---------------- PTX helpers (all non-arch-'a'; compile for sm_103) --------
__device__ __forceinline__ uint32_t smem_u32(const void* p) {
    uint32_t a;
    asm("{ .reg .u64 t; cvta.to.shared.u64 t, %1; cvt.u32.u64 %0, t; }" : "=r"(a) : "l"(p));
    return a;
}
__device__ __forceinline__ void cp16(uint32_t dst, const void* src) {
    asm volatile("cp.async.cg.shared.global [%0], [%1], 16;" :: "r"(dst), "l"(src));
}
#define CP_COMMIT() asm volatile("cp.async.commit_group;" ::: "memory")
#define CP_WAIT1()  asm volatile("cp.async.wait_group 1;" ::: "memory")

__device__ __forceinline__ void ldm4(uint32_t* r, uint32_t addr) {
    asm volatile("ldmatrix.sync.aligned.m8n8.x4.shared.b16 {%0,%1,%2,%3}, [%4];"
                 : "=r"(r[0]), "=r"(r[1]), "=r"(r[2]), "=r"(r[3]) : "r"(addr));
}
__device__ __forceinline__ void mma16816(float* c, const uint32_t* a, const uint32_t* b) {
    asm volatile(
        "mma.sync.aligned.m16n8k16.row.col.f32.bf16.bf16.f32 "
        "{%0,%1,%2,%3}, {%4,%5,%6,%7}, {%8,%9}, {%0,%1,%2,%3};"
        : "+f"(c[0]), "+f"(c[1]), "+f"(c[2]), "+f"(c[3])
        : "r"(a[0]), "r"(a[1]), "r"(a[2]), "r"(a[3]), "r"(b[0]), "r"(b[1]));
}

// ---------------- GEMM: C = A @ B^T, bf16-split (hh + hl + lh) --------------
// CTA tile 128x128, BK=32 (64B rows). 8 warps, warp tile 32(m) x 64(n).
// smem per stage: Ah, Al, Bh, Bl each 128x32 bf16 (8KB) = 32KB; 2 stages = 64KB.
#define TILE_B   8192
#define STAGE_B  (4 * TILE_B)
#define SMEM_DYN (2 * STAGE_B)
#define SB ((size_t)SEQ * DIM)

// swizzled byte offset within one tile for (row, 16B-chunk kc)
__device__ __forceinline__ uint32_t swz(int row, int kc) {
    return (uint32_t)(row * 64 + ((kc ^ ((row >> 1) & 3)) << 4));
}

// MODE 0: scores = alpha * Q @ Enc^T          -> Cf (fp32)
// MODE 1: ctx    = AW @ EncT^T                -> g_ch/g_cl (bf16 split)
// MODE 2: out    = tanh([Q|ctx] @ W^T + b)*m  -> Cf (fp32)
template <int MODE>
__global__ __launch_bounds__(256) void k_gemm(
    float* __restrict__ Cf, const float* __restrict__ bias,
    const float* __restrict__ mask, float alpha)
{
    extern __shared__ char smem[];
    const uint32_t sm = smem_u32(smem);

    const int tid = threadIdx.x;
    const int lane = tid & 31, wid = tid >> 5;
    const int wm = wid & 3, wn = wid >> 2;       // 4 m-warps x 2 n-warps
    const int b  = blockIdx.z;
    const int m0 = blockIdx.y * 128;
    const int n0 = blockIdx.x * 128;

    const bf16 *Ah, *Al, *A2h = nullptr, *A2l = nullptr, *Bh, *Bl;
    int K, lda, ldb;
    if (MODE == 0) {
        Ah = g_qh + (size_t)b * SB;  Al = g_ql + (size_t)b * SB;
        Bh = g_eh + (size_t)b * SB;  Bl = g_el + (size_t)b * SB;
        K = DIM; lda = DIM; ldb = DIM;
    } else if (MODE == 1) {
        Ah = g_awh + (size_t)b * SB; Al = g_awl + (size_t)b * SB;
        Bh = g_eth + (size_t)b * SB; Bl = g_etl + (size_t)b * SB;
        K = SEQ; lda = SEQ; ldb = SEQ;
    } else {
        Ah = g_qh;  Al = g_ql;       // rows indexed by global m (0..16383)
        A2h = g_ch; A2l = g_cl;
        Bh = g_wh;  Bl = g_wl;
        K = 2 * DIM; lda = DIM; ldb = 2 * DIM;
    }
    const int C = K >> 5;   // chunks of 32

    // ---- load: 4 tiles x 512 16B-chunks, 256 threads -> 2 chunks/tile/thread
#define LOAD_CHUNK(c, stg)                                                       \
    do {                                                                         \
        const int k0_ = (c) * 32;                                                \
        const bf16 *ah_, *al_; int ka_;                                          \
        if (MODE == 2 && k0_ >= DIM) { ah_ = A2h; al_ = A2l; ka_ = k0_ - DIM; }  \
        else                         { ah_ = Ah;  al_ = Al;  ka_ = k0_; }        \
        const uint32_t sb_ = sm + (stg) * STAGE_B;                               \
        _Pragma("unroll")                                                        \
        for (int i_ = 0; i_ < 2; i_++) {                                         \
            int idx_ = i_ * 256 + tid;                                           \
            int row_ = idx_ >> 2, kc_ = idx_ & 3;                                \
            uint32_t d_ = swz(row_, kc_);                                        \
            const char* pa_ = (const char*)(ah_ + (size_t)(m0 + row_) * lda + ka_) + kc_ * 16; \
            const char* pl_ = (const char*)(al_ + (size_t)(m0 + row_) * lda + ka_) + kc_ * 16; \
            const char* pb_ = (const char*)(Bh + (size_t)(n0 + row_) * ldb + k0_) + kc_ * 16;  \
            const char* pc_ = (const char*)(Bl + (size_t)(n0 + row_) * ldb + k0_) + kc_ * 16;  \
            cp16(sb_ + d_, pa_);                                                 \
            cp16(sb_ + TILE_B + d_, pl_);                                        \
            cp16(sb_ + 2 * TILE_B + d_, pb_);                                    \
            cp16(sb_ + 3 * TILE_B + d_, pc_);                                    \
        }                                                                        \
    } while (0)

    // ---- per-lane ldmatrix address precomputes
    const int ar = lane & 15, ktop = lane >> 4;
    int aoff[2], axr[2];
#pragma unroll
    for (int mi = 0; mi < 2; mi++) {
        int row = wm * 32 + mi * 16 + ar;
        aoff[mi] = row * 64; axr[mi] = (row >> 1) & 3;
    }
    const int bmat = lane >> 3;
    const int bkadd = bmat & 1;
    const int brl = ((bmat >> 1) << 3) + (lane & 7);
    int boff[4], bxr[4];
#pragma unroll
    for (int g = 0; g < 4; g++) {
        int nrow = wn * 64 + g * 16 + brl;
        boff[g] = nrow * 64; bxr[g] = (nrow >> 1) & 3;
    }

    float acc[2][8][4];
#pragma unroll
    for (int i = 0; i < 2; i++)
#pragma unroll
        for (int j = 0; j < 8; j++)
#pragma unroll
            for (int q = 0; q < 4; q++) acc[i][j][q] = 0.f;

    LOAD_CHUNK(0, 0); CP_COMMIT();
    LOAD_CHUNK(1, 1); CP_COMMIT();

    for (int c = 0; c < C; c++) {
        CP_WAIT1();
        __syncthreads();
        const uint32_t sb = sm + (c & 1) * STAGE_B;
#pragma unroll
        for (int ks = 0; ks < 2; ks++) {
            const int kb = ks * 2;
            uint32_t afr[2][2][4];
#pragma unroll
            for (int mi = 0; mi < 2; mi++)
#pragma unroll
                for (int v = 0; v < 2; v++)
                    ldm4(afr[mi][v],
                         sb + v * TILE_B + aoff[mi] + (((kb + ktop) ^ axr[mi]) << 4));
            uint32_t bfr[4][2][4];
#pragma unroll
            for (int g = 0; g < 4; g++)
#pragma unroll
                for (int v = 0; v < 2; v++)
                    ldm4(bfr[g][v],
                         sb + (2 + v) * TILE_B + boff[g] + (((kb + bkadd) ^ bxr[g]) << 4));
#pragma unroll
            for (int mi = 0; mi < 2; mi++)
#pragma unroll
                for (int nj = 0; nj < 8; nj++) {
                    const int g = nj >> 1, h = (nj & 1) * 2;
                    mma16816(acc[mi][nj], afr[mi][0], &bfr[g][0][h]);  // hh
                    mma16816(acc[mi][nj], afr[mi][0], &bfr[g][1][h]);  // h*l
                    mma16816(acc[mi][nj], afr[mi][1], &bfr[g][0][h]);  // l*h
                }
        }
        __syncthreads();
        if (c + 2 < C) LOAD_CHUNK(c + 2, c & 1);
        CP_COMMIT();
    }
#undef LOAD_CHUNK

    // ---- epilogue from registers
    const int qr = lane >> 2, qc = lane & 3;
#pragma unroll
    for (int mi = 0; mi < 2; mi++)
#pragma unroll
        for (int nj = 0; nj < 8; nj++)
#pragma unroll
            for (int half = 0; half < 2; half++) {
                const int row = m0 + wm * 32 + mi * 16 + qr + half * 8;
                const int col = n0 + wn * 64 + nj * 8 + qc * 2;
                const float v0 = acc[mi][nj][half * 2 + 0];
                const float v1 = acc[mi][nj][half * 2 + 1];
                if (MODE == 0) {
                    float2 o = make_float2(v0 * alpha, v1 * alpha);
                    *(float2*)(Cf + (size_t)b * SEQ * SEQ + (size_t)row * SEQ + col) = o;
                } else if (MODE == 1) {
                    size_t o = (size_t)b * SB + (size_t)row * DIM + col;
                    __nv_bfloat162 H, L;
                    H.x = __float2bfloat16_rn(v0);
                    H.y = __float2bfloat16_rn(v1);
                    L.x = __float2bfloat16_rn(v0 - __bfloat162float(H.x));
                    L.y = __float2bfloat16_rn(v1 - __bfloat162float(H.y));
                    *(__nv_bfloat162*)(g_ch + o) = H;
                    *(__nv_bfloat162*)(g_cl + o) = L;
                } else {
                    const float mk = mask[row];
                    float2 o = make_float2(tanhf(v0 + bias[col]) * mk,
                                           tanhf(v1 + bias[col + 1]) * mk);
                    *(float2*)(Cf + (size_t)row * DIM + col) = o;
                }
            }
}

// ---------------- fp32 -> bf16 hi/lo split (elementwise, x4) ----------------
// T=0: -> g_qh/g_ql ; T=1: -> g_wh/g_wl
template <int T>
__global__ __launch_bounds__(256) void k_split(const float4* __restrict__ src, int n4)
{
    int i = blockIdx.x * 256 + threadIdx.x;
    if (i >= n4) return;
    float4 v = src[i];
    union { bf16 h[4]; uint2 u; } H, L;
    H.h[0] = __float2bfloat16_rn(v.x); L.h[0] = __float2bfloat16_rn(v.x - __bfloat162float(H.h[0]));
    H.h[1] = __float2bfloat16_rn(v.y); L.h[1] = __float2bfloat16_rn(v.y - __bfloat162float(H.h[1]));
    H.h[2] = __float2bfloat16_rn(v.z); L.h[2] = __float2bfloat16_rn(v.z - __bfloat162float(H.h[2]));
    H.h[3] = __float2bfloat16_rn(v.w); L.h[3] = __float2bfloat16_rn(v.w - __bfloat162float(H.h[3]));
    uint2* hi = (uint2*)(T == 0 ? g_qh : g_wh);
    uint2* lo = (uint2*)(T == 0 ? g_ql : g_wl);
    hi[i] = H.u; lo[i] = L.u;
}

// ------- Enc: split (plain) + split-transpose (per batch, 32x32 tiles) ------
__global__ __launch_bounds__(1024) void k_split_trans(const float* __restrict__ E)
{
    __shared__ float t[32][33];
    const int b = blockIdx.z, e0 = blockIdx.y * 32, d0 = blockIdx.x * 32;
    const int tx = threadIdx.x, ty = threadIdx.y;
    const float* Eb = E + (size_t)b * SB;

    float v = Eb[(size_t)(e0 + ty) * DIM + d0 + tx];
    size_t o = (size_t)b * SB + (size_t)(e0 + ty) * DIM + d0 + tx;
    bf16 h = __float2bfloat16_rn(v);
    g_eh[o] = h;
    g_el[o] = __float2bfloat16_rn(v - __bfloat162float(h));
    t[ty][tx] = v;
    __syncthreads();
    float u = t[tx][ty];
    size_t ot = (size_t)b * SB + (size_t)(d0 + ty) * SEQ + e0 + tx;
    bf16 hh = __float2bfloat16_rn(u);
    g_eth[ot] = hh;
    g_etl[ot] = __float2bfloat16_rn(u - __bfloat162float(hh));
}

// ---------------- softmax (in place) + bf16 hi/lo split out -----------------
__global__ __launch_bounds__(256) void k_softmax_split(float* __restrict__ w)
{
    float* row = w + (size_t)blockIdx.x * SEQ;
    const int t = threadIdx.x;
    float a = row[t];
    float b = row[t + 256];

    __shared__ float red[8];
    float m = fmaxf(a, b);
#pragma unroll
    for (int o = 16; o > 0; o >>= 1) m = fmaxf(m, __shfl_xor_sync(0xffffffffu, m, o));
    if ((t & 31) == 0) red[t >> 5] = m;
    __syncthreads();
    float M = fmaxf(fmaxf(fmaxf(red[0], red[1]), fmaxf(red[2], red[3])),
                    fmaxf(fmaxf(red[4], red[5]), fmaxf(red[6], red[7])));
    __syncthreads();
    float e0 = __expf(a - M), e1 = __expf(b - M);
    float s = e0 + e1;
#pragma unroll
    for (int o = 16; o > 0; o >>= 1) s += __shfl_xor_sync(0xffffffffu, s, o);
    if ((t & 31) == 0) red[t >> 5] = s;
    __syncthreads();
    float S = red[0] + red[1] + red[2] + red[3] + red[4] + red[5] + red[6] + red[7];

    float inv = 1.0f / S;
    float v0 = e0 * inv, v1 = e1 * inv;
    row[t] = v0;
    row[t + 256] = v1;

    size_t base = (size_t)blockIdx.x * SEQ;
    bf16 h0 = __float2bfloat16_rn(v0);
    bf16 h1 = __float2bfloat16_rn(v1);
    g_awh[base + t] = h0;
    g_awl[base + t] = __float2bfloat16_rn(v0 - __bfloat162float(h0));
    g_awh[base + t + 256] = h1;
    g_awl[base + t + 256] = __float2bfloat16_rn(v1 - __bfloat162float(h1));
}

// ---------------------------------------------------------------------------
extern "C" void kernel_launch(void* const* d_in, const int* in_sizes, int n_in,
                              void* d_out, int out_size)
{
    const float* Q    = (const float*)d_in[0];
    const float* Enc  = (const float*)d_in[1];
    const float* mask = (const float*)d_in[2];
    const float* W    = (const float*)d_in[3];
    const float* bias = (const float*)d_in[4];

    float* out_masked  = (float*)d_out;
    float* out_weights = (float*)d_out + NELEM;

    static bool attr_done = false;
    if (!attr_done) {
        cudaFuncSetAttribute(k_gemm<0>, cudaFuncAttributeMaxDynamicSharedMemorySize, SMEM_DYN);
        cudaFuncSetAttribute(k_gemm<1>, cudaFuncAttributeMaxDynamicSharedMemorySize, SMEM_DYN);
        cudaFuncSetAttribute(k_gemm<2>, cudaFuncAttributeMaxDynamicSharedMemorySize, SMEM_DYN);
        attr_done = true;
    }

    const float alpha = 1.0f / sqrtf((float)DIM);

    // 1) splits
    k_split<0><<<(int)(NELEM / 4 / 256), 256>>>((const float4*)Q, (int)(NELEM / 4));
    k_split<1><<<(int)((size_t)DIM * 2 * DIM / 4 / 256), 256>>>((const float4*)W,
                                                                (int)((size_t)DIM * 2 * DIM / 4));
    {
        dim3 g(DIM / 32, SEQ / 32, BATCH), blk(32, 32);
        k_split_trans<<<g, blk>>>(Enc);
    }

    // 2) scores = alpha * Q @ Enc^T -> out_weights (fp32)
    {
        dim3 g(SEQ / 128, SEQ / 128, BATCH);
        k_gemm<0><<<g, 256, SMEM_DYN>>>(out_weights, nullptr, nullptr, alpha);
    }
    // 3) softmax + split
    k_softmax_split<<<BATCH * SEQ, 256>>>(out_weights);
    // 4) ctx = AW @ EncT^T -> g_ch/g_cl
    {
        dim3 g(DIM / 128, SEQ / 128, BATCH);
        k_gemm<1><<<g, 256, SMEM_DYN>>>(nullptr, nullptr, nullptr, 1.0f);
    }
    // 5) out = tanh([Q|ctx] @ W^T + bias) * mask
    {
        dim3 g(DIM / 128, (BATCH * SEQ) / 128, 1);
        k_gemm<2><<<g, 256, SMEM_DYN>>>(out_masked, bias, mask, 1.0f);
    }
}